// round 1
// baseline (speedup 1.0000x reference)
#include <cuda_runtime.h>
#include <math.h>

#define HH 512
#define WW 512
#define BB 2
#define C1 16
#define C2 32
#define NM 16
#define NPIX (BB*HH*WW)

// ---------------- scratch (static __device__, no allocations) ----------------
__device__ __align__(16) float g_gray[NPIX];
__device__ __align__(16) float g_grad[NPIX];
__device__ __align__(16) float g_x1[BB*C1*HH*WW];
__device__ __align__(16) float g_x2[BB*C2*HH*WW];
__device__ int   g_markers[NPIX];
__device__ __align__(16) float g_d0[NPIX];
__device__ __align__(16) float g_d1[NPIX];
__device__ __align__(16) float g_bias[NPIX];
__device__ __align__(16) float g_lab0[NPIX*NM];
__device__ __align__(16) float g_lab1[NPIX*NM];

// ---------------- grayscale ----------------
__global__ __launch_bounds__(256) void k_gray(const float* __restrict__ img) {
    int i = blockIdx.x * 256 + threadIdx.x;
    if (i >= NPIX) return;
    int b = i / (HH*WW);
    int p = i - b*HH*WW;
    const float* base = img + (size_t)b*3*HH*WW;
    float r  = base[p];
    float g  = base[HH*WW + p];
    float bl = base[2*HH*WW + p];
    g_gray[i] = 0.2989f*r + 0.587f*g + 0.114f*bl;
}

// ---------------- Sobel gradient magnitude (cross-correlation, SAME, zero pad) ----------------
__global__ __launch_bounds__(256) void k_sobel(const float* __restrict__ Kx,
                                               const float* __restrict__ Ky) {
    int i = blockIdx.x * 256 + threadIdx.x;
    if (i >= NPIX) return;
    int b = i / (HH*WW);
    int p = i - b*HH*WW;
    int y = p / WW, x = p - y*WW;
    const float* g = g_gray + b*HH*WW;
    float gx = 0.f, gy = 0.f;
    #pragma unroll
    for (int dy = 0; dy < 3; dy++) {
        #pragma unroll
        for (int dx = 0; dx < 3; dx++) {
            int yy = y + dy - 1, xx = x + dx - 1;
            float v = 0.f;
            if (yy >= 0 && yy < HH && xx >= 0 && xx < WW) v = g[yy*WW + xx];
            gx += v * Kx[dy*3 + dx];
            gy += v * Ky[dy*3 + dx];
        }
    }
    g_grad[i] = hypotf(gx, gy);
}

// ---------------- conv1: 1 -> 16, ReLU ----------------
__global__ __launch_bounds__(256) void k_conv1(const float* __restrict__ w1,
                                               const float* __restrict__ b1) {
    __shared__ float sw[C1*9];
    __shared__ float sb[C1];
    int tid = threadIdx.x;
    if (tid < C1*9) sw[tid] = w1[tid];
    if (tid < C1)   sb[tid] = b1[tid];
    __syncthreads();

    int i = blockIdx.x * 256 + tid;
    if (i >= NPIX) return;
    int b = i / (HH*WW);
    int p = i - b*HH*WW;
    int y = p / WW, x = p - y*WW;
    const float* g = g_gray + b*HH*WW;
    float v[9];
    #pragma unroll
    for (int dy = 0; dy < 3; dy++)
        #pragma unroll
        for (int dx = 0; dx < 3; dx++) {
            int yy = y + dy - 1, xx = x + dx - 1;
            float t = 0.f;
            if (yy >= 0 && yy < HH && xx >= 0 && xx < WW) t = g[yy*WW + xx];
            v[dy*3 + dx] = t;
        }
    #pragma unroll
    for (int co = 0; co < C1; co++) {
        float acc = sb[co];
        #pragma unroll
        for (int t = 0; t < 9; t++) acc += v[t] * sw[co*9 + t];
        g_x1[((b*C1 + co)*HH + y)*WW + x] = fmaxf(acc, 0.f);
    }
}

// ---------------- conv2: 16 -> 32, ReLU, tiled ----------------
__global__ __launch_bounds__(256) void k_conv2(const float* __restrict__ w2,
                                               const float* __restrict__ b2) {
    __shared__ __align__(16) float s_in[C1*324];      // [ci][18][18]
    __shared__ __align__(16) float s_w[C1*9*C2];      // [ci][tap][co]
    __shared__ float s_b[C2];
    int tx = threadIdx.x, ty = threadIdx.y;
    int tid = ty*16 + tx;
    int b = blockIdx.z;
    int x0 = blockIdx.x*16, y0 = blockIdx.y*16;

    for (int i = tid; i < C1*324; i += 256) {
        int ci = i / 324, r = (i % 324) / 18, c = i % 18;
        int gy = y0 + r - 1, gx = x0 + c - 1;
        float v = 0.f;
        if (gy >= 0 && gy < HH && gx >= 0 && gx < WW)
            v = g_x1[((b*C1 + ci)*HH + gy)*WW + gx];
        s_in[i] = v;
    }
    for (int i = tid; i < C1*9*C2; i += 256) {
        int ci = i / (9*C2); int rem = i % (9*C2);
        int tap = rem / C2;  int co = rem % C2;
        s_w[i] = w2[(co*C1 + ci)*9 + tap];
    }
    if (tid < C2) s_b[tid] = b2[tid];
    __syncthreads();

    float acc[C2];
    #pragma unroll
    for (int co = 0; co < C2; co++) acc[co] = s_b[co];

    for (int ci = 0; ci < C1; ci++) {
        const float* sp = &s_in[ci*324];
        #pragma unroll
        for (int tap = 0; tap < 9; tap++) {
            int dy = tap / 3, dx = tap % 3;
            float v = sp[(ty+dy)*18 + tx+dx];
            const float4* wp = (const float4*)&s_w[(ci*9 + tap)*C2];
            #pragma unroll
            for (int q = 0; q < C2/4; q++) {
                float4 w4 = wp[q];
                acc[q*4+0] += v * w4.x;
                acc[q*4+1] += v * w4.y;
                acc[q*4+2] += v * w4.z;
                acc[q*4+3] += v * w4.w;
            }
        }
    }
    int y = y0 + ty, x = x0 + tx;
    #pragma unroll
    for (int co = 0; co < C2; co++)
        g_x2[((b*C2 + co)*HH + y)*WW + x] = fmaxf(acc[co], 0.f);
}

// ---------------- conv3: 32 -> 16, softmax, argmax -> markers ----------------
__global__ __launch_bounds__(256) void k_conv3(const float* __restrict__ w3,
                                               const float* __restrict__ b3) {
    extern __shared__ float dynsh[];
    float* s_in = dynsh;               // C2*324
    float* s_w  = dynsh + C2*324;      // [ci][tap][co]  C2*9*NM
    float* s_b  = s_w + C2*9*NM;       // NM
    int tx = threadIdx.x, ty = threadIdx.y;
    int tid = ty*16 + tx;
    int b = blockIdx.z;
    int x0 = blockIdx.x*16, y0 = blockIdx.y*16;

    for (int i = tid; i < C2*324; i += 256) {
        int ci = i / 324, r = (i % 324) / 18, c = i % 18;
        int gy = y0 + r - 1, gx = x0 + c - 1;
        float v = 0.f;
        if (gy >= 0 && gy < HH && gx >= 0 && gx < WW)
            v = g_x2[((b*C2 + ci)*HH + gy)*WW + gx];
        s_in[i] = v;
    }
    for (int i = tid; i < C2*9*NM; i += 256) {
        int ci = i / (9*NM); int rem = i % (9*NM);
        int tap = rem / NM;  int co = rem % NM;
        s_w[i] = w3[(co*C2 + ci)*9 + tap];
    }
    if (tid < NM) s_b[tid] = b3[tid];
    __syncthreads();

    float acc[NM];
    #pragma unroll
    for (int co = 0; co < NM; co++) acc[co] = s_b[co];

    for (int ci = 0; ci < C2; ci++) {
        const float* sp = &s_in[ci*324];
        #pragma unroll
        for (int tap = 0; tap < 9; tap++) {
            int dy = tap / 3, dx = tap % 3;
            float v = sp[(ty+dy)*18 + tx+dx];
            const float4* wp = (const float4*)&s_w[(ci*9 + tap)*NM];
            #pragma unroll
            for (int q = 0; q < NM/4; q++) {
                float4 w4 = wp[q];
                acc[q*4+0] += v * w4.x;
                acc[q*4+1] += v * w4.y;
                acc[q*4+2] += v * w4.z;
                acc[q*4+3] += v * w4.w;
            }
        }
    }
    // softmax (monotone, but done faithfully) then argmax, first-index ties
    float m = acc[0];
    #pragma unroll
    for (int c = 1; c < NM; c++) m = fmaxf(m, acc[c]);
    float e[NM]; float s = 0.f;
    #pragma unroll
    for (int c = 0; c < NM; c++) { e[c] = expf(acc[c] - m); s += e[c]; }
    float best = -1.f; int bi = 0;
    #pragma unroll
    for (int c = 0; c < NM; c++) {
        float pv = e[c] / s;
        if (pv > best) { best = pv; bi = c; }
    }
    int y = y0 + ty, x = x0 + tx;
    g_markers[(b*HH + y)*WW + x] = bi;
}

// ---------------- init: d0 and one-hot labeled ----------------
__global__ __launch_bounds__(256) void k_init() {
    int i = blockIdx.x * 256 + threadIdx.x;
    if (i >= NPIX) return;
    int m = g_markers[i];
    g_d0[i] = (m > 0) ? 0.f : 1e6f;
    float* lp = &g_lab0[(size_t)i*NM];
    #pragma unroll
    for (int c = 0; c < NM; c++) lp[c] = (c == m) ? 1.f : 0.f;
}

// ---------------- SDF chamfer step: d = min(d, minpool3(d) + 1) ----------------
__global__ __launch_bounds__(256) void k_sdf(int inIdx) {
    const float* din = inIdx ? g_d1 : g_d0;
    float* dout      = inIdx ? g_d0 : g_d1;
    int i = blockIdx.x * 256 + threadIdx.x;
    if (i >= NPIX) return;
    int b = i / (HH*WW);
    int p = i - b*HH*WW;
    int y = p / WW, x = p - y*WW;
    const float* d = din + b*HH*WW;
    float mn = INFINITY;
    #pragma unroll
    for (int dy = -1; dy <= 1; dy++)
        #pragma unroll
        for (int dx = -1; dx <= 1; dx++) {
            int yy = y + dy, xx = x + dx;
            if (yy >= 0 && yy < HH && xx >= 0 && xx < WW)
                mn = fminf(mn, d[yy*WW + xx]);
        }
    dout[i] = fminf(d[y*WW + x], mn + 1.f);
}

// ---------------- bias = gradient + sdf ----------------
__global__ __launch_bounds__(256) void k_bias() {
    int i = blockIdx.x * 256 + threadIdx.x;
    if (i >= NPIX) return;
    float sdf = -fminf(g_d0[i], 20.f) * 0.05f;
    g_bias[i] = g_grad[i] + sdf;
}

// ---------------- flood iteration: softmax(avgpool3(lab) + bias) ----------------
__global__ __launch_bounds__(256) void k_flood(int inIdx) {
    __shared__ __align__(16) float s[NM*324];   // [c][18][18]
    const float* in = inIdx ? g_lab1 : g_lab0;
    float* out      = inIdx ? g_lab0 : g_lab1;
    int tx = threadIdx.x, ty = threadIdx.y;
    int tid = ty*16 + tx;
    int b = blockIdx.z;
    int x0 = blockIdx.x*16, y0 = blockIdx.y*16;

    // cooperative load of 18x18 pixel halo tile, 16 channels (4 float4s each)
    for (int q = tid; q < 324*4; q += 256) {
        int p = q >> 2, c4 = q & 3;
        int r = p / 18, c = p - r*18;
        int gy = y0 + r - 1, gx = x0 + c - 1;
        float4 v = make_float4(0.f, 0.f, 0.f, 0.f);
        if (gy >= 0 && gy < HH && gx >= 0 && gx < WW)
            v = *(const float4*)&in[((size_t)((b*HH + gy)*WW + gx))*NM + c4*4];
        int base = r*18 + c;
        s[(c4*4 + 0)*324 + base] = v.x;
        s[(c4*4 + 1)*324 + base] = v.y;
        s[(c4*4 + 2)*324 + base] = v.z;
        s[(c4*4 + 3)*324 + base] = v.w;
    }
    __syncthreads();

    int y = y0 + ty, x = x0 + tx;
    int pix = (b*HH + y)*WW + x;
    float bv = g_bias[pix];

    float l[NM];
    #pragma unroll
    for (int c = 0; c < NM; c++) {
        const float* sp = &s[c*324];
        float a = 0.f;
        #pragma unroll
        for (int dy = 0; dy < 3; dy++) {
            a += sp[(ty+dy)*18 + tx + 0];
            a += sp[(ty+dy)*18 + tx + 1];
            a += sp[(ty+dy)*18 + tx + 2];
        }
        l[c] = a * (1.f/9.f) + bv;
    }
    float m = l[0];
    #pragma unroll
    for (int c = 1; c < NM; c++) m = fmaxf(m, l[c]);
    float ssum = 0.f;
    #pragma unroll
    for (int c = 0; c < NM; c++) { l[c] = expf(l[c] - m); ssum += l[c]; }
    float inv = 1.0f / ssum;
    float* op = &out[(size_t)pix*NM];
    #pragma unroll
    for (int c4 = 0; c4 < 4; c4++) {
        float4 v = make_float4(l[c4*4+0]*inv, l[c4*4+1]*inv, l[c4*4+2]*inv, l[c4*4+3]*inv);
        *(float4*)&op[c4*4] = v;
    }
}

// ---------------- final argmax ----------------
__global__ __launch_bounds__(256) void k_argmax(int* __restrict__ outp) {
    int i = blockIdx.x * 256 + threadIdx.x;
    if (i >= NPIX) return;
    const float* lp = &g_lab0[(size_t)i*NM];
    float best = lp[0]; int bi = 0;
    #pragma unroll
    for (int c = 1; c < NM; c++) {
        float v = lp[c];
        if (v > best) { best = v; bi = c; }
    }
    outp[i] = bi;
}

// ---------------- launch ----------------
extern "C" void kernel_launch(void* const* d_in, const int* in_sizes, int n_in,
                              void* d_out, int out_size) {
    const float* image = (const float*)d_in[0];
    const float* Kx    = (const float*)d_in[1];
    const float* Ky    = (const float*)d_in[2];
    const float* w1    = (const float*)d_in[3];
    const float* b1    = (const float*)d_in[4];
    const float* w2    = (const float*)d_in[5];
    const float* b2    = (const float*)d_in[6];
    const float* w3    = (const float*)d_in[7];
    const float* b3    = (const float*)d_in[8];

    int nblk = NPIX / 256;
    dim3 tb(16, 16), tg(WW/16, HH/16, BB);

    k_gray<<<nblk, 256>>>(image);
    k_sobel<<<nblk, 256>>>(Kx, Ky);
    k_conv1<<<nblk, 256>>>(w1, b1);
    k_conv2<<<tg, tb>>>(w2, b2);

    size_t sh3 = (size_t)(C2*324 + C2*9*NM + NM) * sizeof(float);
    cudaFuncSetAttribute(k_conv3, cudaFuncAttributeMaxDynamicSharedMemorySize, (int)sh3);
    k_conv3<<<tg, tb, sh3>>>(w3, b3);

    k_init<<<nblk, 256>>>();
    for (int k = 0; k < 20; k++) k_sdf<<<nblk, 256>>>(k & 1);
    k_bias<<<nblk, 256>>>();
    for (int k = 0; k < 50; k++) k_flood<<<tg, tb>>>(k & 1);
    k_argmax<<<nblk, 256>>>((int*)d_out);
}

// round 2
// speedup vs baseline: 2.0313x; 2.0313x over previous
#include <cuda_runtime.h>
#include <math.h>

#define HH 512
#define WW 512
#define BB 2
#define C1 16
#define C2 32
#define NM 16
#define NPIX (BB*HH*WW)
#define FLOOD_ITERS 16   // softmax-diffusion reaches its exact fp32 fixed point by ~iter 12

// ---------------- scratch (static __device__, no allocations) ----------------
__device__ __align__(16) float g_gray[NPIX];
__device__ __align__(16) float g_grad[NPIX];
__device__ __align__(16) float g_x1[BB*C1*HH*WW];
__device__ __align__(16) float g_x2[BB*C2*HH*WW];
__device__ int   g_markers[NPIX];
__device__ __align__(16) float g_d0[NPIX];
__device__ __align__(16) float g_d1[NPIX];
__device__ __align__(16) float g_bias[NPIX];
__device__ __align__(16) float g_lab0[NPIX*NM];
__device__ __align__(16) float g_lab1[NPIX*NM];

// ---------------- grayscale ----------------
__global__ __launch_bounds__(256) void k_gray(const float* __restrict__ img) {
    int i = blockIdx.x * 256 + threadIdx.x;
    if (i >= NPIX) return;
    int b = i / (HH*WW);
    int p = i - b*HH*WW;
    const float* base = img + (size_t)b*3*HH*WW;
    float r  = base[p];
    float g  = base[HH*WW + p];
    float bl = base[2*HH*WW + p];
    g_gray[i] = 0.2989f*r + 0.587f*g + 0.114f*bl;
}

// ---------------- Sobel gradient magnitude ----------------
__global__ __launch_bounds__(256) void k_sobel(const float* __restrict__ Kx,
                                               const float* __restrict__ Ky) {
    int i = blockIdx.x * 256 + threadIdx.x;
    if (i >= NPIX) return;
    int b = i / (HH*WW);
    int p = i - b*HH*WW;
    int y = p / WW, x = p - y*WW;
    const float* g = g_gray + b*HH*WW;
    float gx = 0.f, gy = 0.f;
    #pragma unroll
    for (int dy = 0; dy < 3; dy++) {
        #pragma unroll
        for (int dx = 0; dx < 3; dx++) {
            int yy = y + dy - 1, xx = x + dx - 1;
            float v = 0.f;
            if (yy >= 0 && yy < HH && xx >= 0 && xx < WW) v = g[yy*WW + xx];
            gx += v * Kx[dy*3 + dx];
            gy += v * Ky[dy*3 + dx];
        }
    }
    g_grad[i] = hypotf(gx, gy);
}

// ---------------- conv1: 1 -> 16, ReLU ----------------
__global__ __launch_bounds__(256) void k_conv1(const float* __restrict__ w1,
                                               const float* __restrict__ b1) {
    __shared__ float sw[C1*9];
    __shared__ float sb[C1];
    int tid = threadIdx.x;
    if (tid < C1*9) sw[tid] = w1[tid];
    if (tid < C1)   sb[tid] = b1[tid];
    __syncthreads();

    int i = blockIdx.x * 256 + tid;
    if (i >= NPIX) return;
    int b = i / (HH*WW);
    int p = i - b*HH*WW;
    int y = p / WW, x = p - y*WW;
    const float* g = g_gray + b*HH*WW;
    float v[9];
    #pragma unroll
    for (int dy = 0; dy < 3; dy++)
        #pragma unroll
        for (int dx = 0; dx < 3; dx++) {
            int yy = y + dy - 1, xx = x + dx - 1;
            float t = 0.f;
            if (yy >= 0 && yy < HH && xx >= 0 && xx < WW) t = g[yy*WW + xx];
            v[dy*3 + dx] = t;
        }
    #pragma unroll
    for (int co = 0; co < C1; co++) {
        float acc = sb[co];
        #pragma unroll
        for (int t = 0; t < 9; t++) acc += v[t] * sw[co*9 + t];
        g_x1[((b*C1 + co)*HH + y)*WW + x] = fmaxf(acc, 0.f);
    }
}

// ---------------- conv2: 16 -> 32, ReLU, tiled ----------------
__global__ __launch_bounds__(256) void k_conv2(const float* __restrict__ w2,
                                               const float* __restrict__ b2) {
    __shared__ __align__(16) float s_in[C1*324];      // [ci][18][18]
    __shared__ __align__(16) float s_w[C1*9*C2];      // [ci][tap][co]
    __shared__ float s_b[C2];
    int tx = threadIdx.x, ty = threadIdx.y;
    int tid = ty*16 + tx;
    int b = blockIdx.z;
    int x0 = blockIdx.x*16, y0 = blockIdx.y*16;

    for (int i = tid; i < C1*324; i += 256) {
        int ci = i / 324, r = (i % 324) / 18, c = i % 18;
        int gy = y0 + r - 1, gx = x0 + c - 1;
        float v = 0.f;
        if (gy >= 0 && gy < HH && gx >= 0 && gx < WW)
            v = g_x1[((b*C1 + ci)*HH + gy)*WW + gx];
        s_in[i] = v;
    }
    for (int i = tid; i < C1*9*C2; i += 256) {
        int ci = i / (9*C2); int rem = i % (9*C2);
        int tap = rem / C2;  int co = rem % C2;
        s_w[i] = w2[(co*C1 + ci)*9 + tap];
    }
    if (tid < C2) s_b[tid] = b2[tid];
    __syncthreads();

    float acc[C2];
    #pragma unroll
    for (int co = 0; co < C2; co++) acc[co] = s_b[co];

    for (int ci = 0; ci < C1; ci++) {
        const float* sp = &s_in[ci*324];
        #pragma unroll
        for (int tap = 0; tap < 9; tap++) {
            int dy = tap / 3, dx = tap % 3;
            float v = sp[(ty+dy)*18 + tx+dx];
            const float4* wp = (const float4*)&s_w[(ci*9 + tap)*C2];
            #pragma unroll
            for (int q = 0; q < C2/4; q++) {
                float4 w4 = wp[q];
                acc[q*4+0] += v * w4.x;
                acc[q*4+1] += v * w4.y;
                acc[q*4+2] += v * w4.z;
                acc[q*4+3] += v * w4.w;
            }
        }
    }
    int y = y0 + ty, x = x0 + tx;
    #pragma unroll
    for (int co = 0; co < C2; co++)
        g_x2[((b*C2 + co)*HH + y)*WW + x] = fmaxf(acc[co], 0.f);
}

// ---------------- conv3: 32 -> 16, softmax, argmax -> markers ----------------
__global__ __launch_bounds__(256) void k_conv3(const float* __restrict__ w3,
                                               const float* __restrict__ b3) {
    extern __shared__ float dynsh[];
    float* s_in = dynsh;               // C2*324
    float* s_w  = dynsh + C2*324;      // [ci][tap][co]  C2*9*NM
    float* s_b  = s_w + C2*9*NM;       // NM
    int tx = threadIdx.x, ty = threadIdx.y;
    int tid = ty*16 + tx;
    int b = blockIdx.z;
    int x0 = blockIdx.x*16, y0 = blockIdx.y*16;

    for (int i = tid; i < C2*324; i += 256) {
        int ci = i / 324, r = (i % 324) / 18, c = i % 18;
        int gy = y0 + r - 1, gx = x0 + c - 1;
        float v = 0.f;
        if (gy >= 0 && gy < HH && gx >= 0 && gx < WW)
            v = g_x2[((b*C2 + ci)*HH + gy)*WW + gx];
        s_in[i] = v;
    }
    for (int i = tid; i < C2*9*NM; i += 256) {
        int ci = i / (9*NM); int rem = i % (9*NM);
        int tap = rem / NM;  int co = rem % NM;
        s_w[i] = w3[(co*C2 + ci)*9 + tap];
    }
    if (tid < NM) s_b[tid] = b3[tid];
    __syncthreads();

    float acc[NM];
    #pragma unroll
    for (int co = 0; co < NM; co++) acc[co] = s_b[co];

    for (int ci = 0; ci < C2; ci++) {
        const float* sp = &s_in[ci*324];
        #pragma unroll
        for (int tap = 0; tap < 9; tap++) {
            int dy = tap / 3, dx = tap % 3;
            float v = sp[(ty+dy)*18 + tx+dx];
            const float4* wp = (const float4*)&s_w[(ci*9 + tap)*NM];
            #pragma unroll
            for (int q = 0; q < NM/4; q++) {
                float4 w4 = wp[q];
                acc[q*4+0] += v * w4.x;
                acc[q*4+1] += v * w4.y;
                acc[q*4+2] += v * w4.z;
                acc[q*4+3] += v * w4.w;
            }
        }
    }
    // softmax then argmax (first-index ties) — softmax is monotone, kept faithful
    float m = acc[0];
    #pragma unroll
    for (int c = 1; c < NM; c++) m = fmaxf(m, acc[c]);
    float e[NM]; float s = 0.f;
    #pragma unroll
    for (int c = 0; c < NM; c++) { e[c] = expf(acc[c] - m); s += e[c]; }
    float best = -1.f; int bi = 0;
    #pragma unroll
    for (int c = 0; c < NM; c++) {
        float pv = e[c] / s;
        if (pv > best) { best = pv; bi = c; }
    }
    int y = y0 + ty, x = x0 + tx;
    g_markers[(b*HH + y)*WW + x] = bi;
}

// ---------------- init: d0 and one-hot labeled ----------------
__global__ __launch_bounds__(256) void k_init() {
    int i = blockIdx.x * 256 + threadIdx.x;
    if (i >= NPIX) return;
    int m = g_markers[i];
    g_d0[i] = (m > 0) ? 0.f : 1e6f;
    float* lp = &g_lab0[(size_t)i*NM];
    #pragma unroll
    for (int c = 0; c < NM; c++) lp[c] = (c == m) ? 1.f : 0.f;
}

// ---------------- SDF chamfer step ----------------
__global__ __launch_bounds__(256) void k_sdf(int inIdx) {
    const float* din = inIdx ? g_d1 : g_d0;
    float* dout      = inIdx ? g_d0 : g_d1;
    int i = blockIdx.x * 256 + threadIdx.x;
    if (i >= NPIX) return;
    int b = i / (HH*WW);
    int p = i - b*HH*WW;
    int y = p / WW, x = p - y*WW;
    const float* d = din + b*HH*WW;
    float mn = INFINITY;
    #pragma unroll
    for (int dy = -1; dy <= 1; dy++)
        #pragma unroll
        for (int dx = -1; dx <= 1; dx++) {
            int yy = y + dy, xx = x + dx;
            if (yy >= 0 && yy < HH && xx >= 0 && xx < WW)
                mn = fminf(mn, d[yy*WW + xx]);
        }
    dout[i] = fminf(d[y*WW + x], mn + 1.f);
}

// ---------------- bias = gradient + sdf ----------------
__global__ __launch_bounds__(256) void k_bias() {
    int i = blockIdx.x * 256 + threadIdx.x;
    if (i >= NPIX) return;
    float sdf = -fminf(g_d0[i], 20.f) * 0.05f;
    g_bias[i] = g_grad[i] + sdf;
}

// ---------------- flood iteration: softmax(avgpool3(lab) + bias) ----------------
__global__ __launch_bounds__(256) void k_flood(int inIdx) {
    __shared__ __align__(16) float s[NM*324];   // [c][18][18]
    const float* in = inIdx ? g_lab1 : g_lab0;
    float* out      = inIdx ? g_lab0 : g_lab1;
    int tx = threadIdx.x, ty = threadIdx.y;
    int tid = ty*16 + tx;
    int b = blockIdx.z;
    int x0 = blockIdx.x*16, y0 = blockIdx.y*16;

    for (int q = tid; q < 324*4; q += 256) {
        int p = q >> 2, c4 = q & 3;
        int r = p / 18, c = p - r*18;
        int gy = y0 + r - 1, gx = x0 + c - 1;
        float4 v = make_float4(0.f, 0.f, 0.f, 0.f);
        if (gy >= 0 && gy < HH && gx >= 0 && gx < WW)
            v = *(const float4*)&in[((size_t)((b*HH + gy)*WW + gx))*NM + c4*4];
        int base = r*18 + c;
        s[(c4*4 + 0)*324 + base] = v.x;
        s[(c4*4 + 1)*324 + base] = v.y;
        s[(c4*4 + 2)*324 + base] = v.z;
        s[(c4*4 + 3)*324 + base] = v.w;
    }
    __syncthreads();

    int y = y0 + ty, x = x0 + tx;
    int pix = (b*HH + y)*WW + x;
    float bv = g_bias[pix];

    float l[NM];
    #pragma unroll
    for (int c = 0; c < NM; c++) {
        const float* sp = &s[c*324];
        float a = 0.f;
        #pragma unroll
        for (int dy = 0; dy < 3; dy++) {
            a += sp[(ty+dy)*18 + tx + 0];
            a += sp[(ty+dy)*18 + tx + 1];
            a += sp[(ty+dy)*18 + tx + 2];
        }
        l[c] = a * (1.f/9.f) + bv;
    }
    float m = l[0];
    #pragma unroll
    for (int c = 1; c < NM; c++) m = fmaxf(m, l[c]);
    float ssum = 0.f;
    #pragma unroll
    for (int c = 0; c < NM; c++) { l[c] = __expf(l[c] - m); ssum += l[c]; }
    float inv = 1.0f / ssum;
    float* op = &out[(size_t)pix*NM];
    #pragma unroll
    for (int c4 = 0; c4 < 4; c4++) {
        float4 v = make_float4(l[c4*4+0]*inv, l[c4*4+1]*inv, l[c4*4+2]*inv, l[c4*4+3]*inv);
        *(float4*)&op[c4*4] = v;
    }
}

// ---------------- final argmax ----------------
__global__ __launch_bounds__(256) void k_argmax(int* __restrict__ outp) {
    int i = blockIdx.x * 256 + threadIdx.x;
    if (i >= NPIX) return;
    const float* lp = &g_lab0[(size_t)i*NM];
    float best = lp[0]; int bi = 0;
    #pragma unroll
    for (int c = 1; c < NM; c++) {
        float v = lp[c];
        if (v > best) { best = v; bi = c; }
    }
    outp[i] = bi;
}

// ---------------- launch ----------------
extern "C" void kernel_launch(void* const* d_in, const int* in_sizes, int n_in,
                              void* d_out, int out_size) {
    const float* image = (const float*)d_in[0];
    const float* Kx    = (const float*)d_in[1];
    const float* Ky    = (const float*)d_in[2];
    const float* w1    = (const float*)d_in[3];
    const float* b1    = (const float*)d_in[4];
    const float* w2    = (const float*)d_in[5];
    const float* b2    = (const float*)d_in[6];
    const float* w3    = (const float*)d_in[7];
    const float* b3    = (const float*)d_in[8];

    int nblk = NPIX / 256;
    dim3 tb(16, 16), tg(WW/16, HH/16, BB);

    k_gray<<<nblk, 256>>>(image);
    k_sobel<<<nblk, 256>>>(Kx, Ky);
    k_conv1<<<nblk, 256>>>(w1, b1);
    k_conv2<<<tg, tb>>>(w2, b2);

    size_t sh3 = (size_t)(C2*324 + C2*9*NM + NM) * sizeof(float);
    cudaFuncSetAttribute(k_conv3, cudaFuncAttributeMaxDynamicSharedMemorySize, (int)sh3);
    k_conv3<<<tg, tb, sh3>>>(w3, b3);

    k_init<<<nblk, 256>>>();
    for (int k = 0; k < 20; k++) k_sdf<<<nblk, 256>>>(k & 1);
    k_bias<<<nblk, 256>>>();
    // Flood: the softmax-diffusion reaches its exact fp32 fixed point (uniform
    // 1/16 per pixel) within ~12 iterations; iterations beyond that are bitwise
    // no-ops. 16 (even) keeps the final buffer in g_lab0, matching 50 iterations.
    for (int k = 0; k < FLOOD_ITERS; k++) k_flood<<<tg, tb>>>(k & 1);
    k_argmax<<<nblk, 256>>>((int*)d_out);
}

// round 3
// speedup vs baseline: 390.8126x; 192.4000x over previous
#include <cuda_runtime.h>

// LearnableWatershedWithSDF — exact closed form.
//
// The reference's flood loop is p <- softmax(avgpool3(p) + bias) where bias is
// channel-constant per pixel, so softmax(l + b) == softmax(l) and the iteration
// is a global contraction on the channel spread (factor ~1/16 per iteration).
// Within ~10-12 of the 50 iterations every pixel reaches the EXACT fp32 fixed
// point: all 16 probabilities identically 1/16 (logit differences underflow to
// 0, exp(0)=1, 1/16 is exact in binary). argmax with first-index tie-breaking
// (jnp.argmax) of an exact-uniform vector is 0 at every pixel, for ANY input.
//
// Verified empirically: both a faithful 50-iteration fp32 implementation and a
// 16-iteration __expf implementation produced rel_err == 0.0 against the JAX
// reference (bitwise-identical int labels), confirming full convergence to the
// input-independent fixed point. The reference function is identically zero.

__global__ __launch_bounds__(256) void k_zero(int4* __restrict__ out, int n4) {
    int i = blockIdx.x * 256 + threadIdx.x;
    if (i < n4) out[i] = make_int4(0, 0, 0, 0);
}

__global__ __launch_bounds__(256) void k_zero_tail(int* __restrict__ out,
                                                   int start, int n) {
    int i = start + blockIdx.x * 256 + threadIdx.x;
    if (i < n) out[i] = 0;
}

extern "C" void kernel_launch(void* const* d_in, const int* in_sizes, int n_in,
                              void* d_out, int out_size) {
    (void)d_in; (void)in_sizes; (void)n_in;
    int n4 = out_size >> 2;                 // vectorized int4 stores
    if (n4 > 0) {
        int blocks = (n4 + 255) / 256;
        k_zero<<<blocks, 256>>>((int4*)d_out, n4);
    }
    int done = n4 << 2;
    if (done < out_size) {                  // tail (out_size not multiple of 4)
        int rem = out_size - done;
        int blocks = (rem + 255) / 256;
        k_zero_tail<<<blocks, 256>>>((int*)d_out, done, out_size);
    }
}